// round 13
// baseline (speedup 1.0000x reference)
#include <cuda_runtime.h>

#define R 16
#define A 8
#define THREADS 256

__device__ __forceinline__ float ex2f(float x) {
    float r;
    asm("ex2.approx.f32 %0, %1;" : "=f"(r) : "f"(x));
    return r;
}

__global__ __launch_bounds__(THREADS)   // no min-blocks cap: let ptxas pick regs, no spills
void t2fls_kernel(const float* __restrict__ x_in,
                  const float* __restrict__ W,
                  const float* __restrict__ c1,
                  const float* __restrict__ c2,
                  float* __restrict__ out, int n)
{
    // d = U-L per (rule, row). Column t is touched only by thread t.
    __shared__ float shD[R][THREADS];                       // 16 KB
    // Coefficients in c1-sorted rule order, natural feature order (float4-loadable).
    __shared__ __align__(16) float sh_nm[R][A];             // negated centers
    __shared__ __align__(16) float sh_gb[R][A];             // -0.5*log2(e)/smax^2 (U)
    __shared__ __align__(16) float sh_gs[R][A];             // -0.5*log2(e)/smin^2 (L)
    // Per sorted slot j: (c1s[j], c2s[j], as_float(q[j]*THREADS), c2[p1[j]])
    __shared__ float4 shScan[R];
    __shared__ int   sh_p1[R], sh_inv1[R], sh_p2[R];
    __shared__ float sh_c1s[R], sh_c2s[R];

    int t = threadIdx.x;

    // ---- Phase A: parallel rank-sort of c1 (threads 0..15) and c2 (threads 16..31) ----
    if (t < R) {
        float cj = c1[t];
        int rank = 0;
        #pragma unroll
        for (int i = 0; i < R; i++) {
            float ci = c1[i];
            rank += (ci < cj) || (ci == cj && i < t);   // stable
        }
        sh_p1[rank] = t;
        sh_inv1[t] = rank;
        sh_c1s[rank] = cj;
    } else if (t < 2 * R) {
        int j = t - R;
        float cj = c2[j];
        int rank = 0;
        #pragma unroll
        for (int i = 0; i < R; i++) {
            float ci = c2[i];
            rank += (ci < cj) || (ci == cj && i < j);   // stable
        }
        sh_p2[rank] = j;
        sh_c2s[rank] = cj;
    }
    __syncthreads();

    // ---- Phase B: coefficient transform into c1-sorted layout ----
    if (t < R * A) {
        int r = t >> 3, a = t & 7;
        // offsets = A*r + a == t ; m = W[t], s1 = W[t+1], s2 = W[t+2]
        float m  = W[t];
        float s1 = W[t + 1];
        float s2 = W[t + 2];
        float smax = fmaxf(s1, s2);
        float smin = fminf(s1, s2);
        const float k = -0.5f * 1.44269504088896340736f;  // -0.5 * log2(e)
        int slot = sh_inv1[r];
        sh_nm[slot][a] = -m;
        sh_gb[slot][a] = k / (smax * smax);
        sh_gs[slot][a] = k / (smin * smin);
    }
    if (t < R) {
        int q = sh_inv1[sh_p2[t]];   // slot (in c1-order storage) of rule p2[t]
        shScan[t] = make_float4(sh_c1s[t], sh_c2s[t],
                                __int_as_float(q * THREADS),
                                c2[sh_p1[t]]);           // c2 value of rule at c1-slot t
    }
    __syncthreads();

    int i = blockIdx.x * THREADS + t;
    if (i >= n) return;

    // Load the 8-feature row with two float4s.
    const float4* xp = (const float4*)(x_in + (size_t)i * A);
    float4 xa = xp[0];
    float4 xb = xp[1];

    float s0 = 0.f, t0 = 0.f;     // sum(c1*L), sum(L)
    float s0r = 0.f, t0r = 0.f;   // sum(c2*U), sum(U)

    #pragma unroll
    for (int j = 0; j < R; j++) {
        float4 nm0 = *(const float4*)&sh_nm[j][0];
        float4 nm1 = *(const float4*)&sh_nm[j][4];
        float4 gb0 = *(const float4*)&sh_gb[j][0];
        float4 gb1 = *(const float4*)&sh_gb[j][4];
        float4 gs0 = *(const float4*)&sh_gs[j][0];
        float4 gs1 = *(const float4*)&sh_gs[j][4];

        float su = 0.f, sl = 0.f, d, e;
        d = xa.x + nm0.x; e = d * d; su = fmaf(e, gb0.x, su); sl = fmaf(e, gs0.x, sl);
        d = xa.y + nm0.y; e = d * d; su = fmaf(e, gb0.y, su); sl = fmaf(e, gs0.y, sl);
        d = xa.z + nm0.z; e = d * d; su = fmaf(e, gb0.z, su); sl = fmaf(e, gs0.z, sl);
        d = xa.w + nm0.w; e = d * d; su = fmaf(e, gb0.w, su); sl = fmaf(e, gs0.w, sl);
        d = xb.x + nm1.x; e = d * d; su = fmaf(e, gb1.x, su); sl = fmaf(e, gs1.x, sl);
        d = xb.y + nm1.y; e = d * d; su = fmaf(e, gb1.y, su); sl = fmaf(e, gs1.y, sl);
        d = xb.z + nm1.z; e = d * d; su = fmaf(e, gb1.z, su); sl = fmaf(e, gs1.z, sl);
        d = xb.w + nm1.w; e = d * d; su = fmaf(e, gb1.w, su); sl = fmaf(e, gs1.w, sl);

        float U = ex2f(su);   // prod_a mu_big  = exp2(sum of scaled exponents)
        float L = ex2f(sl);   // prod_a mu_small

        float4 sc = shScan[j];
        s0  = fmaf(sc.x, L, s0);   t0  += L;    // sc.x = c1 of this (sorted) rule
        s0r = fmaf(sc.w, U, s0r);  t0r += U;    // sc.w = c2 of this rule
        shD[j][t] = U - L;
    }

    // Division-free KM scans: all denominators are positive (t0 = sum L > 0;
    // left adds cumulative (U-L) >= 0; right denom = partial mix of L and U sums > 0),
    // so  p1/q1 < p2/q2  <=>  p1*q2 < p2*q1.  Track the best fraction, divide once.
    float bpL = s0,  bqL = t0;    // running min fraction (left)
    float bpR = s0r, bqR = t0r;   // running max fraction (right)
    float cs = s0,  ct = t0;      // cumulative numerator/denominator (left)
    float csr = s0r, ctr = t0r;   // cumulative numerator/denominator (right)
    const float* shDf = &shD[0][0];
    #pragma unroll
    for (int j = 0; j < R; j++) {
        float4 sc = shScan[j];
        // Left scan: storage is already c1-sorted -> compile-time offsets.
        float dj = shD[j][t];
        cs = fmaf(sc.x, dj, cs);      // p_j = s0 + sum c1s*(U-L)
        ct += dj;                     // q_j = t0 + sum (U-L)
        bool takeL = (cs * bqL) < (bpL * ct);
        bpL = takeL ? cs : bpL;
        bqL = takeL ? ct : bqL;
        // Right scan: c2-sorted order via runtime slot offset (same-thread column).
        int off = __float_as_int(sc.z);
        float dq = shDf[off + t];     // = U - L of rule p2[j]
        csr = fmaf(sc.y, -dq, csr);   // p_j = s0r + sum c2s*(L-U)
        ctr -= dq;                    // q_j = t0r + sum (L-U)
        bool takeR = (csr * bqR) > (bpR * ctr);
        bpR = takeR ? csr : bpR;
        bqR = takeR ? ctr : bqR;
    }

    float left  = __fdividef(bpL, bqL);
    float right = __fdividef(bpR, bqR);
    out[i] = 0.5f * (left + right);
}

extern "C" void kernel_launch(void* const* d_in, const int* in_sizes, int n_in,
                              void* d_out, int out_size) {
    const float* x  = (const float*)d_in[0];
    const float* W  = (const float*)d_in[1];
    const float* c1 = (const float*)d_in[2];
    const float* c2 = (const float*)d_in[3];
    float* out = (float*)d_out;
    int n = out_size;  // one output per row

    int blocks = (n + THREADS - 1) / THREADS;
    t2fls_kernel<<<blocks, THREADS>>>(x, W, c1, c2, out, n);
}

// round 15
// speedup vs baseline: 1.1218x; 1.1218x over previous
#include <cuda_runtime.h>

#define R 16
#define A 8
#define THREADS 256

__device__ __forceinline__ float ex2f(float x) {
    float r;
    asm("ex2.approx.f32 %0, %1;" : "=f"(r) : "f"(x));
    return r;
}

__global__ __launch_bounds__(THREADS)   // no min-blocks cap: let ptxas pick regs
void t2fls_kernel(const float* __restrict__ x_in,
                  const float* __restrict__ W,
                  const float* __restrict__ c1,
                  const float* __restrict__ c2,
                  float* __restrict__ out, int n)
{
    // d = U-L per (rule, row). Column t is touched only by thread t.
    __shared__ float shD[R][THREADS];                       // 16 KB
    // Coefficients in c1-sorted rule order. Scalar-read in the hot loop
    // (broadcast LDS.32 feeding FMAs directly keeps the live set small;
    // vector loads here trigger ptxas load-batching -> 105 regs. Measured.)
    __shared__ float sh_nm[R][A];             // negated centers
    __shared__ float sh_gb[R][A];             // -0.5*log2(e)/smax^2 (U)
    __shared__ float sh_gs[R][A];             // -0.5*log2(e)/smin^2 (L)
    // Per sorted slot j: (c1s[j], c2s[j], as_float(q[j]*THREADS), c2[p1[j]])
    __shared__ float4 shScan[R];
    __shared__ int   sh_p1[R], sh_inv1[R], sh_p2[R];
    __shared__ float sh_c1s[R], sh_c2s[R];

    int t = threadIdx.x;

    // ---- Phase A: parallel rank-sort of c1 (threads 0..15) and c2 (threads 16..31) ----
    if (t < R) {
        float cj = c1[t];
        int rank = 0;
        #pragma unroll
        for (int i = 0; i < R; i++) {
            float ci = c1[i];
            rank += (ci < cj) || (ci == cj && i < t);   // stable
        }
        sh_p1[rank] = t;
        sh_inv1[t] = rank;
        sh_c1s[rank] = cj;
    } else if (t < 2 * R) {
        int j = t - R;
        float cj = c2[j];
        int rank = 0;
        #pragma unroll
        for (int i = 0; i < R; i++) {
            float ci = c2[i];
            rank += (ci < cj) || (ci == cj && i < j);   // stable
        }
        sh_p2[rank] = j;
        sh_c2s[rank] = cj;
    }
    __syncthreads();

    // ---- Phase B: coefficient transform into c1-sorted layout ----
    if (t < R * A) {
        int r = t >> 3, a = t & 7;
        // offsets = A*r + a == t ; m = W[t], s1 = W[t+1], s2 = W[t+2]
        float m  = W[t];
        float s1 = W[t + 1];
        float s2 = W[t + 2];
        float smax = fmaxf(s1, s2);
        float smin = fminf(s1, s2);
        const float k = -0.5f * 1.44269504088896340736f;  // -0.5 * log2(e)
        int slot = sh_inv1[r];
        sh_nm[slot][a] = -m;
        sh_gb[slot][a] = k / (smax * smax);
        sh_gs[slot][a] = k / (smin * smin);
    }
    if (t < R) {
        int q = sh_inv1[sh_p2[t]];   // slot (in c1-order storage) of rule p2[t]
        shScan[t] = make_float4(sh_c1s[t], sh_c2s[t],
                                __int_as_float(q * THREADS),
                                c2[sh_p1[t]]);           // c2 value of rule at c1-slot t
    }
    __syncthreads();

    int i = blockIdx.x * THREADS + t;
    if (i >= n) return;

    // Load the 8-feature row with two float4s.
    const float4* xp = (const float4*)(x_in + (size_t)i * A);
    float4 a0 = xp[0];
    float4 a1 = xp[1];
    float x[A] = {a0.x, a0.y, a0.z, a0.w, a1.x, a1.y, a1.z, a1.w};

    float s0 = 0.f, t0 = 0.f;     // sum(c1*L), sum(L)
    float s0r = 0.f, t0r = 0.f;   // sum(c2*U), sum(U)

    #pragma unroll
    for (int j = 0; j < R; j++) {
        float su = 0.f, sl = 0.f;
        #pragma unroll
        for (int a = 0; a < A; a++) {
            float d = x[a] + sh_nm[j][a];
            float e = d * d;
            su = fmaf(e, sh_gb[j][a], su);
            sl = fmaf(e, sh_gs[j][a], sl);
        }
        float U = ex2f(su);   // prod_a mu_big  = exp2(sum of scaled exponents)
        float L = ex2f(sl);   // prod_a mu_small

        float4 sc = shScan[j];
        s0  = fmaf(sc.x, L, s0);   t0  += L;    // sc.x = c1 of this (sorted) rule
        s0r = fmaf(sc.w, U, s0r);  t0r += U;    // sc.w = c2 of this rule
        shD[j][t] = U - L;
    }

    // Division-free KM scans: all denominators are positive (t0 = sum L > 0;
    // left adds cumulative (U-L) >= 0; right denom is a partial mix of L/U sums > 0),
    // so  p1/q1 < p2/q2  <=>  p1*q2 < p2*q1.  Track the best fraction, divide once.
    float bpL = s0,  bqL = t0;    // running min fraction (left)
    float bpR = s0r, bqR = t0r;   // running max fraction (right)
    float cs = s0,  ct = t0;      // cumulative numerator/denominator (left)
    float csr = s0r, ctr = t0r;   // cumulative numerator/denominator (right)
    const float* shDf = &shD[0][0];
    #pragma unroll
    for (int j = 0; j < R; j++) {
        float4 sc = shScan[j];
        // Left scan: storage is already c1-sorted -> compile-time offsets.
        float dj = shD[j][t];
        cs = fmaf(sc.x, dj, cs);      // p_j = s0 + sum c1s*(U-L)
        ct += dj;                     // q_j = t0 + sum (U-L)
        bool takeL = (cs * bqL) < (bpL * ct);
        bpL = takeL ? cs : bpL;
        bqL = takeL ? ct : bqL;
        // Right scan: c2-sorted order via runtime slot offset (same-thread column).
        int off = __float_as_int(sc.z);
        float dq = shDf[off + t];     // = U - L of rule p2[j]
        csr = fmaf(sc.y, -dq, csr);   // p_j = s0r + sum c2s*(L-U)
        ctr -= dq;                    // q_j = t0r + sum (L-U)
        bool takeR = (csr * bqR) > (bpR * ctr);
        bpR = takeR ? csr : bpR;
        bqR = takeR ? ctr : bqR;
    }

    float left  = __fdividef(bpL, bqL);
    float right = __fdividef(bpR, bqR);
    out[i] = 0.5f * (left + right);
}

extern "C" void kernel_launch(void* const* d_in, const int* in_sizes, int n_in,
                              void* d_out, int out_size) {
    const float* x  = (const float*)d_in[0];
    const float* W  = (const float*)d_in[1];
    const float* c1 = (const float*)d_in[2];
    const float* c2 = (const float*)d_in[3];
    float* out = (float*)d_out;
    int n = out_size;  // one output per row

    int blocks = (n + THREADS - 1) / THREADS;
    t2fls_kernel<<<blocks, THREADS>>>(x, W, c1, c2, out, n);
}

// round 17
// speedup vs baseline: 1.1237x; 1.0017x over previous
#include <cuda_runtime.h>

#define R 16
#define A 8
#define THREADS 256

__device__ __forceinline__ float ex2f(float x) {
    float r;
    asm("ex2.approx.f32 %0, %1;" : "=f"(r) : "f"(x));
    return r;
}

__global__ __launch_bounds__(THREADS)   // no min-blocks cap: let ptxas pick regs
void t2fls_kernel(const float* __restrict__ x_in,
                  const float* __restrict__ W,
                  const float* __restrict__ c1,
                  const float* __restrict__ c2,
                  float* __restrict__ out, int n)
{
    // d = U-L per (rule, row). Column t is touched only by thread t.
    __shared__ float shD[R][THREADS];                       // 16 KB
    // Coefficients in c1-sorted rule order. ALL hot-loop shared reads are
    // scalar broadcasts: a float4 (LDS.128) inside the fully-unrolled loop
    // gets batched by ptxas across all 16 iterations -> 105 regs (measured
    // R4/R12/R13/R15). Scalar broadcasts stay at ~44 regs (measured R1).
    __shared__ float sh_nm[R][A];             // negated centers
    __shared__ float sh_gb[R][A];             // -0.5*log2(e)/smax^2 (U)
    __shared__ float sh_gs[R][A];             // -0.5*log2(e)/smin^2 (L)
    __shared__ float sh_c1s[R];               // c1 sorted ascending
    __shared__ float sh_c2of1[R];             // c2 value of the rule at c1-slot j
    __shared__ float sh_c2s[R];               // c2 sorted ascending
    __shared__ int   sh_qoff[R];              // c1-slot of rule p2[j], * THREADS
    __shared__ int   sh_p1[R], sh_inv1[R], sh_p2[R];

    int t = threadIdx.x;

    // ---- Phase A: parallel rank-sort of c1 (threads 0..15) and c2 (threads 16..31) ----
    if (t < R) {
        float cj = c1[t];
        int rank = 0;
        #pragma unroll
        for (int i = 0; i < R; i++) {
            float ci = c1[i];
            rank += (ci < cj) || (ci == cj && i < t);   // stable
        }
        sh_p1[rank] = t;
        sh_inv1[t] = rank;
        sh_c1s[rank] = cj;
    } else if (t < 2 * R) {
        int j = t - R;
        float cj = c2[j];
        int rank = 0;
        #pragma unroll
        for (int i = 0; i < R; i++) {
            float ci = c2[i];
            rank += (ci < cj) || (ci == cj && i < j);   // stable
        }
        sh_p2[rank] = j;
        sh_c2s[rank] = cj;
    }
    __syncthreads();

    // ---- Phase B: coefficient transform into c1-sorted layout ----
    if (t < R * A) {
        int r = t >> 3, a = t & 7;
        // offsets = A*r + a == t ; m = W[t], s1 = W[t+1], s2 = W[t+2]
        float m  = W[t];
        float s1 = W[t + 1];
        float s2 = W[t + 2];
        float smax = fmaxf(s1, s2);
        float smin = fminf(s1, s2);
        const float k = -0.5f * 1.44269504088896340736f;  // -0.5 * log2(e)
        int slot = sh_inv1[r];
        sh_nm[slot][a] = -m;
        sh_gb[slot][a] = k / (smax * smax);
        sh_gs[slot][a] = k / (smin * smin);
    }
    if (t < R) {
        sh_qoff[t]  = sh_inv1[sh_p2[t]] * THREADS;  // c1-slot of rule p2[t]
        sh_c2of1[t] = c2[sh_p1[t]];                 // c2 of rule at c1-slot t
    }
    __syncthreads();

    int i = blockIdx.x * THREADS + t;
    if (i >= n) return;

    // Load the 8-feature row with two float4s.
    const float4* xp = (const float4*)(x_in + (size_t)i * A);
    float4 a0 = xp[0];
    float4 a1 = xp[1];
    float x[A] = {a0.x, a0.y, a0.z, a0.w, a1.x, a1.y, a1.z, a1.w};

    float s0 = 0.f, t0 = 0.f;     // sum(c1*L), sum(L)
    float s0r = 0.f, t0r = 0.f;   // sum(c2*U), sum(U)

    #pragma unroll
    for (int j = 0; j < R; j++) {
        float su = 0.f, sl = 0.f;
        #pragma unroll
        for (int a = 0; a < A; a++) {
            float d = x[a] + sh_nm[j][a];
            float e = d * d;
            su = fmaf(e, sh_gb[j][a], su);
            sl = fmaf(e, sh_gs[j][a], sl);
        }
        float U = ex2f(su);   // prod_a mu_big  = exp2(sum of scaled exponents)
        float L = ex2f(sl);   // prod_a mu_small

        s0  = fmaf(sh_c1s[j],   L, s0);   t0  += L;
        s0r = fmaf(sh_c2of1[j], U, s0r);  t0r += U;
        shD[j][t] = U - L;
    }

    // Division-free KM scans: all denominators are positive (t0 = sum L > 0;
    // left adds cumulative (U-L) >= 0; right denom is a partial mix of L/U sums > 0),
    // so  p1/q1 < p2/q2  <=>  p1*q2 < p2*q1.  Track the best fraction, divide once.
    float bpL = s0,  bqL = t0;    // running min fraction (left)
    float bpR = s0r, bqR = t0r;   // running max fraction (right)
    float cs = s0,  ct = t0;      // cumulative numerator/denominator (left)
    float csr = s0r, ctr = t0r;   // cumulative numerator/denominator (right)
    const float* shDf = &shD[0][0];
    #pragma unroll
    for (int j = 0; j < R; j++) {
        // Left scan: storage is already c1-sorted -> compile-time offsets.
        float dj = shD[j][t];
        cs = fmaf(sh_c1s[j], dj, cs); // p_j = s0 + sum c1s*(U-L)
        ct += dj;                     // q_j = t0 + sum (U-L)
        bool takeL = (cs * bqL) < (bpL * ct);
        bpL = takeL ? cs : bpL;
        bqL = takeL ? ct : bqL;
        // Right scan: c2-sorted order via runtime slot offset (same-thread column).
        float dq = shDf[sh_qoff[j] + t];  // = U - L of rule p2[j]
        csr = fmaf(sh_c2s[j], -dq, csr);  // p_j = s0r + sum c2s*(L-U)
        ctr -= dq;                        // q_j = t0r + sum (L-U)
        bool takeR = (csr * bqR) > (bpR * ctr);
        bpR = takeR ? csr : bpR;
        bqR = takeR ? ctr : bqR;
    }

    float left  = __fdividef(bpL, bqL);
    float right = __fdividef(bpR, bqR);
    out[i] = 0.5f * (left + right);
}

extern "C" void kernel_launch(void* const* d_in, const int* in_sizes, int n_in,
                              void* d_out, int out_size) {
    const float* x  = (const float*)d_in[0];
    const float* W  = (const float*)d_in[1];
    const float* c1 = (const float*)d_in[2];
    const float* c2 = (const float*)d_in[3];
    float* out = (float*)d_out;
    int n = out_size;  // one output per row

    int blocks = (n + THREADS - 1) / THREADS;
    t2fls_kernel<<<blocks, THREADS>>>(x, W, c1, c2, out, n);
}